// round 1
// baseline (speedup 1.0000x reference)
#include <cuda_runtime.h>

// ---------------------------------------------------------------------------
// FrontierLayerVN fused kernel (fp32 baseline)
//
// Pipeline per gathered row m:
//   idx = idx_ligans[m]; sca = S[idx] (256), vec = V[idx] (64x3)
//   vh[h,i]   = sum_c vec[c,i] * Wv1_1[c,h]            (h<64)
//   vn[h]     = ||vh[h,:]||
//   s1[j]     = sum_h vn[h]*Ws1[h,j] + sum_c sca[c]*Ws1[64+c,j]   (j<128)
//   gate[o]   = sigmoid(sum_j s1[j]*Wg1[j,o] + bg1[o])            (o<32)
//   ov[o,i]   = sum_h vh[h,i]*Wv2_1[h,o];  v2 = gate*ov
//   VNLeakyReLU(v2) with Wd1 -> v3
//   s1a       = leaky(s1, 0.01)
//   vh2[h,i]  = sum_c v3[c,i]*Wv1_2[c,h]; vn2 = ||vh2||            (h<32)
//   out[m]    = sum_h vn2[h]*Ws2[h] + sum_j s1a[j]*Ws2[32+j]
// ---------------------------------------------------------------------------

#define NWARPS 8
#define THREADS (NWARPS * 32)

// shared sizes in floats
#define SZ_WV11 4096   // 64x64
#define SZ_WV21 2048   // 64x32
#define SZ_WS1  40960  // 320x128
#define SZ_WG1  4096   // 128x32
#define SZ_BG1  32
#define SZ_WD1  1024   // 32x32
#define SZ_WV12 1024   // 32x32
#define SZ_WS2  160
#define SZ_WEIGHTS (SZ_WV11 + SZ_WV21 + SZ_WS1 + SZ_WG1 + SZ_BG1 + SZ_WD1 + SZ_WV12 + SZ_WS2)
#define SCRATCH_PER_WARP 512
#define SMEM_FLOATS (SZ_WEIGHTS + NWARPS * SCRATCH_PER_WARP)

__global__ __launch_bounds__(THREADS, 1)
void frontier_vn_kernel(
    const float* __restrict__ g_sca,   // (N,256)
    const float* __restrict__ g_vec,   // (N,64,3)
    const int*   __restrict__ g_idx,   // (M,)
    const float* __restrict__ gWv11,   // (64,64)
    const float* __restrict__ gWv21,   // (64,32)
    const float* __restrict__ gWs1,    // (320,128)
    const float* __restrict__ gWg1,    // (128,32)
    const float* __restrict__ gbg1,    // (32,)
    const float* __restrict__ gWd1,    // (32,32)
    const float* __restrict__ gWv12,   // (32,32)
    const float* __restrict__ gWs2,    // (160,)
    float* __restrict__ out,           // (M,)
    int M)
{
    extern __shared__ float sm[];
    float* sWv11 = sm;
    float* sWv21 = sWv11 + SZ_WV11;
    float* sWs1  = sWv21 + SZ_WV21;
    float* sWg1  = sWs1  + SZ_WS1;
    float* sbg1  = sWg1  + SZ_WG1;
    float* sWd1  = sbg1  + SZ_BG1;
    float* sWv12 = sWd1  + SZ_WD1;
    float* sWs2  = sWv12 + SZ_WV12;
    float* scratch = sWs2 + SZ_WS2;

    const int tid = threadIdx.x;

    // ---- cooperative weight staging (float4) ----
    {
        float4* d; const float4* s;
        d = (float4*)sWv11; s = (const float4*)gWv11;
        for (int i = tid; i < SZ_WV11/4; i += THREADS) d[i] = s[i];
        d = (float4*)sWv21; s = (const float4*)gWv21;
        for (int i = tid; i < SZ_WV21/4; i += THREADS) d[i] = s[i];
        d = (float4*)sWs1;  s = (const float4*)gWs1;
        for (int i = tid; i < SZ_WS1/4;  i += THREADS) d[i] = s[i];
        d = (float4*)sWg1;  s = (const float4*)gWg1;
        for (int i = tid; i < SZ_WG1/4;  i += THREADS) d[i] = s[i];
        d = (float4*)sbg1;  s = (const float4*)gbg1;
        for (int i = tid; i < SZ_BG1/4;  i += THREADS) d[i] = s[i];
        d = (float4*)sWd1;  s = (const float4*)gWd1;
        for (int i = tid; i < SZ_WD1/4;  i += THREADS) d[i] = s[i];
        d = (float4*)sWv12; s = (const float4*)gWv12;
        for (int i = tid; i < SZ_WV12/4; i += THREADS) d[i] = s[i];
        d = (float4*)sWs2;  s = (const float4*)gWs2;
        for (int i = tid; i < SZ_WS2/4;  i += THREADS) d[i] = s[i];
    }
    __syncthreads();

    const int warp = tid >> 5;
    const int lane = tid & 31;
    float* ws = scratch + warp * SCRATCH_PER_WARP;
    // scratch regions (floats):
    //  [0,256)   sca        -> later [0,128) s1, [128,224) v2
    //  [256,448) vec        -> later vh   ; [224,320) v3 (vh dead by then)
    //  [448,512) vnorm

    for (int m = blockIdx.x * NWARPS + warp; m < M; m += gridDim.x * NWARPS) {
        const int idx = g_idx[m];
        const float4* gs4 = (const float4*)(g_sca + (size_t)idx * 256);
        const float4* gv4 = (const float4*)(g_vec + (size_t)idx * 192);
        float4 s_a = gs4[lane];
        float4 s_b = gs4[lane + 32];
        float4 v_a = gv4[lane];
        float4 v_b = (lane < 16) ? gv4[lane + 32] : make_float4(0.f,0.f,0.f,0.f);

        __syncwarp();  // prior iteration fully done reading scratch
        ((float4*)ws)[lane]            = s_a;
        ((float4*)ws)[lane + 32]       = s_b;
        ((float4*)(ws + 256))[lane]    = v_a;
        if (lane < 16) ((float4*)(ws + 256))[lane + 32] = v_b;
        __syncwarp();

        // ---- stage 1: vh (lane owns h0=lane, h1=lane+32) ----
        float a0x = 0.f, a0y = 0.f, a0z = 0.f;
        float a1x = 0.f, a1y = 0.f, a1z = 0.f;
        #pragma unroll 8
        for (int c = 0; c < 64; c++) {
            float vx = ws[256 + c*3 + 0];
            float vy = ws[256 + c*3 + 1];
            float vz = ws[256 + c*3 + 2];
            float w0 = sWv11[c*64 + lane];
            float w1 = sWv11[c*64 + 32 + lane];
            a0x += w0*vx; a0y += w0*vy; a0z += w0*vz;
            a1x += w1*vx; a1y += w1*vy; a1z += w1*vz;
        }
        float n0 = sqrtf(a0x*a0x + a0y*a0y + a0z*a0z);
        float n1 = sqrtf(a1x*a1x + a1y*a1y + a1z*a1z);
        __syncwarp();  // everyone done reading vec before overwrite with vh
        ws[256 + lane*3 + 0] = a0x;
        ws[256 + lane*3 + 1] = a0y;
        ws[256 + lane*3 + 2] = a0z;
        ws[256 + (lane+32)*3 + 0] = a1x;
        ws[256 + (lane+32)*3 + 1] = a1y;
        ws[256 + (lane+32)*3 + 2] = a1z;
        ws[448 + lane]      = n0;
        ws[448 + lane + 32] = n1;
        __syncwarp();

        // ---- stage 2: s1[j], lane owns j = lane + 32q ----
        float s0 = 0.f, s1 = 0.f, s2 = 0.f, s3 = 0.f;
        #pragma unroll 8
        for (int k = 0; k < 64; k++) {
            float x = ws[448 + k];
            const float* wr = sWs1 + k * 128;
            s0 += x * wr[lane];
            s1 += x * wr[lane + 32];
            s2 += x * wr[lane + 64];
            s3 += x * wr[lane + 96];
        }
        #pragma unroll 8
        for (int k = 0; k < 256; k++) {
            float x = ws[k];
            const float* wr = sWs1 + (64 + k) * 128;
            s0 += x * wr[lane];
            s1 += x * wr[lane + 32];
            s2 += x * wr[lane + 64];
            s3 += x * wr[lane + 96];
        }
        __syncwarp();  // done reading sca
        ws[lane]      = s0;
        ws[lane + 32] = s1;
        ws[lane + 64] = s2;
        ws[lane + 96] = s3;
        __syncwarp();

        // ---- gate + out_vec (lane owns o = lane) ----
        float g = 0.f;
        #pragma unroll 8
        for (int j = 0; j < 128; j++)
            g += ws[j] * sWg1[j*32 + lane];
        g = 1.f / (1.f + expf(-(g + sbg1[lane])));

        float ox = 0.f, oy = 0.f, oz = 0.f;
        #pragma unroll 8
        for (int h = 0; h < 64; h++) {
            float w = sWv21[h*32 + lane];
            ox += w * ws[256 + h*3 + 0];
            oy += w * ws[256 + h*3 + 1];
            oz += w * ws[256 + h*3 + 2];
        }
        float vx = g * ox, vy = g * oy, vz = g * oz;  // v2[lane]
        __syncwarp();  // done reading vh + s1 region untouched
        ws[128 + lane*3 + 0] = vx;
        ws[128 + lane*3 + 1] = vy;
        ws[128 + lane*3 + 2] = vz;
        __syncwarp();

        // ---- VNLeakyReLU (lane owns o = lane) ----
        float dx = 0.f, dy = 0.f, dz = 0.f;
        #pragma unroll 8
        for (int c = 0; c < 32; c++) {
            float w = sWd1[c*32 + lane];
            dx += w * ws[128 + c*3 + 0];
            dy += w * ws[128 + c*3 + 1];
            dz += w * ws[128 + c*3 + 2];
        }
        float dot = vx*dx + vy*dy + vz*dz;
        float dsq = dx*dx + dy*dy + dz*dz;
        float t = dot / (dsq + 1e-6f);
        float px = vx - t*dx, py = vy - t*dy, pz = vz - t*dz;
        float rx = (dot >= 0.f) ? vx : px;
        float ry = (dot >= 0.f) ? vy : py;
        float rz = (dot >= 0.f) ? vz : pz;
        float ux = 0.2f*vx + 0.8f*rx;
        float uy = 0.2f*vy + 0.8f*ry;
        float uz = 0.2f*vz + 0.8f*rz;
        // write v3 at [224,320) (vh region [256,448) dead; no read overlap)
        ws[224 + lane*3 + 0] = ux;
        ws[224 + lane*3 + 1] = uy;
        ws[224 + lane*3 + 2] = uz;
        __syncwarp();

        // ---- layer 2 (lane owns h = lane) ----
        float bx = 0.f, by = 0.f, bz = 0.f;
        #pragma unroll 8
        for (int c = 0; c < 32; c++) {
            float w = sWv12[c*32 + lane];
            bx += w * ws[224 + c*3 + 0];
            by += w * ws[224 + c*3 + 1];
            bz += w * ws[224 + c*3 + 2];
        }
        float vn2 = sqrtf(bx*bx + by*by + bz*bz);
        float partial = vn2 * sWs2[lane];
        #pragma unroll
        for (int q = 0; q < 4; q++) {
            float x = ws[lane + 32*q];
            x = (x >= 0.f) ? x : 0.01f * x;       // scalar LeakyReLU(0.01)
            partial += x * sWs2[32 + lane + 32*q];
        }
        #pragma unroll
        for (int off = 16; off > 0; off >>= 1)
            partial += __shfl_xor_sync(0xffffffffu, partial, off);
        if (lane == 0) out[m] = partial;
        __syncwarp();
    }
}

extern "C" void kernel_launch(void* const* d_in, const int* in_sizes, int n_in,
                              void* d_out, int out_size)
{
    const float* g_sca  = (const float*)d_in[0];
    const float* g_vec  = (const float*)d_in[1];
    const int*   g_idx  = (const int*)  d_in[2];
    const float* gWv11  = (const float*)d_in[3];
    const float* gWv21  = (const float*)d_in[4];
    const float* gWs1   = (const float*)d_in[5];
    const float* gWg1   = (const float*)d_in[6];
    const float* gbg1   = (const float*)d_in[7];
    const float* gWd1   = (const float*)d_in[8];
    const float* gWv12  = (const float*)d_in[9];
    // d_in[10] = Wv2_2 (unused: only scalar branch of layer 2 is returned)
    const float* gWs2   = (const float*)d_in[11];
    // d_in[12] = Wg_2, d_in[13] = bg_2 (unused)
    float* out = (float*)d_out;
    const int M = in_sizes[2];

    const int smem_bytes = SMEM_FLOATS * (int)sizeof(float);  // 230144 B
    cudaFuncSetAttribute(frontier_vn_kernel,
                         cudaFuncAttributeMaxDynamicSharedMemorySize, smem_bytes);

    int sms = 148;
    cudaDeviceGetAttribute(&sms, cudaDevAttrMultiProcessorCount, 0);

    frontier_vn_kernel<<<sms, THREADS, smem_bytes>>>(
        g_sca, g_vec, g_idx,
        gWv11, gWv21, gWs1, gWg1, gbg1, gWd1, gWv12, gWs2,
        out, M);
}